// round 13
// baseline (speedup 1.0000x reference)
#include <cuda_runtime.h>
#include <cuda_bf16.h>
#include <cuda_fp16.h>
#include <math.h>
#include <stdint.h>

#define WIDTH 128
#define NMAX  50176
#define EMAX  512000
#define TILEB 32768                 // full 128x128 bf16 image tile
#define ATILE 16384                 // 64-row half tile
#define DSTRIDE 132
// smem: Bh[32K] Bl[32K] | union( Ah[16K] Al[16K] , Dst[33792] )
#define SOFF_BH 0
#define SOFF_BL 32768
#define SOFF_AH 65536
#define SOFF_AL 81920
#define DSMEM   99328

// ---- scratch (device globals) ----
__device__ float  g_Q  [NMAX * WIDTH];
__device__ float  g_K  [NMAX * WIDTH];
__device__ __half g_Vh [NMAX * WIDTH];
__device__ float  g_X2 [NMAX * WIDTH];
__device__ float  g_Agg[NMAX * WIDTH];
__device__ float  g_T  [3 * 34 * WIDTH];
__device__ float  g_T81[81 * 3 * WIDTH];
__device__ __half g_T2h[81 * WIDTH];
__device__ unsigned char g_iW[6][2][TILEB];
__device__ unsigned char g_iXh[392 * TILEB];
__device__ unsigned char g_iXl[392 * TILEB];
__device__ int g_cnt [NMAX];
__device__ int g_cur [NMAX];
__device__ int g_base[NMAX + 1];
__device__ int g_esrc[EMAX];
__device__ int g_eidx[EMAX];

__device__ __forceinline__ float gelu1(float x) {
    return 0.5f * x * (1.0f + erff(x * 0.7071067811865475f));
}
__device__ __forceinline__ float gelu_t(float x) {
    float u = 0.7978845608028654f * fmaf(0.044715f * x, x * x, x);
    float t;
    asm("tanh.approx.f32 %0, %1;" : "=f"(t) : "f"(u));
    return 0.5f * x * (1.0f + t);
}
__device__ __forceinline__ int soff(int row, int kc) {
    return row * 256 + ((kc ^ (row & 7)) << 4);
}
__device__ __forceinline__ uint32_t smem_u32(const void* p) {
    uint32_t a;
    asm("{ .reg .u64 t; cvta.to.shared.u64 t, %1; cvt.u32.u64 %0, t; }" : "=r"(a) : "l"(p));
    return a;
}
__device__ __forceinline__ void cpa16(uint32_t s, const void* g) {
    asm volatile("cp.async.ca.shared.global [%0], [%1], 16;" :: "r"(s), "l"(g));
}
__device__ __forceinline__ void ldm4(uint32_t* r, uint32_t a) {
    asm volatile("ldmatrix.sync.aligned.m8n8.x4.shared.b16 {%0,%1,%2,%3}, [%4];"
                 : "=r"(r[0]), "=r"(r[1]), "=r"(r[2]), "=r"(r[3]) : "r"(a));
}
__device__ __forceinline__ void mma16816(float* c, const uint32_t* a, uint32_t b0, uint32_t b1) {
    asm volatile(
        "mma.sync.aligned.m16n8k16.row.col.f32.bf16.bf16.f32 "
        "{%0,%1,%2,%3}, {%4,%5,%6,%7}, {%8,%9}, {%0,%1,%2,%3};"
        : "+f"(c[0]), "+f"(c[1]), "+f"(c[2]), "+f"(c[3])
        : "r"(a[0]), "r"(a[1]), "r"(a[2]), "r"(a[3]), "r"(b0), "r"(b1));
}

// ============================================================================
// Tables
// ============================================================================
__global__ void k_tables(const float* __restrict__ r0w, const float* __restrict__ r1w,
                         const float* __restrict__ r2w,
                         const float* __restrict__ e0, const float* __restrict__ e1,
                         const float* __restrict__ e2, const float* __restrict__ e3,
                         const float* __restrict__ einit, const float* __restrict__ init0)
{
    int j = blockIdx.x, r = blockIdx.y, o = threadIdx.x;
    int c, lr;
    if (r < 6)       { c = 0; lr = r; }
    else if (r < 13) { c = 1; lr = r - 6; }
    else if (r < 16) { c = 2; lr = r - 13; }
    else             { c = 3; lr = r - 16; }
    const float* emb = (c == 0) ? e0 : (c == 1) ? e1 : (c == 2) ? e2 : e3;
    const float* rw  = (j == 0) ? r0w : (j == 1) ? r1w : r2w;

    __shared__ float er[64];
    if (o < 64) er[o] = emb[lr * 64 + o];
    __syncthreads();

    float s = 0.0f;
#pragma unroll
    for (int m = 0; m < 64; m++) s += er[m] * rw[m * WIDTH + o];

    float es = expf(einit[0]) + expf(einit[1]) + expf(einit[2]) + expf(einit[3]);
    float xw = expf(einit[c]) * rsqrtf(es);
    float sf = expf((j == 2) ? init0[3] : init0[2]);
    g_T[(j * 34 + r) * WIDTH + o] = s * xw * sf;
}

__global__ void k_combine()
{
    int j = blockIdx.x, i = blockIdx.y, o = threadIdx.x;
    int d0 = i % 3, d1 = (i / 3) % 3, d2 = (i / 9) % 3, d3 = i / 27;
    float v = g_T[(j * 34 + d0) * WIDTH + o] + g_T[(j * 34 + 6 + d1) * WIDTH + o]
            + g_T[(j * 34 + 13 + d2) * WIDTH + o] + g_T[(j * 34 + 16 + d3) * WIDTH + o];
    g_T81[(i * 3 + j) * WIDTH + o] = v;
    if (j == 2) g_T2h[i * WIDTH + o] = __float2half(v);
}

// ============================================================================
// CSR build
// ============================================================================
__global__ void k_zero(int n)
{
    int i = blockIdx.x * blockDim.x + threadIdx.x;
    if (i < n) { g_cnt[i] = 0; g_cur[i] = 0; }
}
__global__ void k_hist(const int* __restrict__ ei, int e)
{
    for (int i = blockIdx.x * blockDim.x + threadIdx.x; i < e; i += gridDim.x * blockDim.x)
        atomicAdd(&g_cnt[ei[e + i]], 1);
}
__global__ void __launch_bounds__(1024) k_scan(int n, int e)
{
    __shared__ int sp[1024];
    int t = threadIdx.x;
    int chunk = (n + 1023) >> 10;
    int lo = t * chunk, hi = min(lo + chunk, n);
    int s = 0;
    for (int i = lo; i < hi; i++) s += g_cnt[i];
    sp[t] = s;
    __syncthreads();
    for (int d = 1; d < 1024; d <<= 1) {
        int v = (t >= d) ? sp[t - d] : 0;
        __syncthreads();
        if (t >= d) sp[t] += v;
        __syncthreads();
    }
    int run = (t > 0) ? sp[t - 1] : 0;
    for (int i = lo; i < hi; i++) { int c = g_cnt[i]; g_base[i] = run; run += c; }
    if (t == 0) g_base[n] = e;
}
__global__ void k_scatter(const int* __restrict__ ei, const int* __restrict__ ea, int e)
{
    for (int i = blockIdx.x * blockDim.x + threadIdx.x; i < e; i += gridDim.x * blockDim.x) {
        int dst = ei[e + i];
        int4 a = __ldg((const int4*)ea + i);
        int idx = a.x + 3 * a.y + 9 * a.z + 27 * a.w;
        int pos = g_base[dst] + atomicAdd(&g_cur[dst], 1);
        g_esrc[pos] = ei[i];
        g_eidx[pos] = idx;
    }
}

// ============================================================================
// Weight prep (weights 1..5 only; w0 converted in-kernel by PRE)
// ============================================================================
__global__ void __launch_bounds__(256) k_prepw(const float* __restrict__ w1,
    const float* __restrict__ w2, const float* __restrict__ w3,
    const float* __restrict__ w4, const float* __restrict__ w5)
{
    int wi = 1 + (blockIdx.x >> 3), sl = blockIdx.x & 7;
    const float* W = (wi == 1) ? w1 : (wi == 2) ? w2 : (wi == 3) ? w3
                   : (wi == 4) ? w4 : w5;
    int nrow = sl * 16 + (threadIdx.x >> 4);
    int kc = threadIdx.x & 15;
    __nv_bfloat16 h8[8], l8[8];
#pragma unroll
    for (int j = 0; j < 8; j++) {
        float v = W[(kc * 8 + j) * WIDTH + nrow];
        h8[j] = __float2bfloat16(v);
        l8[j] = __float2bfloat16(v - __bfloat162float(h8[j]));
    }
    int off = soff(nrow, kc);
    *(uint4*)(g_iW[wi][0] + off) = *(uint4*)h8;
    *(uint4*)(g_iW[wi][1] + off) = *(uint4*)l8;
}

// ============================================================================
// mma.sync GEMM: 64x128 tile, 512 thr (2x8 warps, 32x16/warp), 2 CTAs/SM.
// bf16 hi/lo 3-pass.
// mode 0: PRE. A <- cvt(x), B <- cvt(w0) in-kernel. Epi: bias+LN -> xx images.
// mode 1: blockIdx.y = step (0=Q,1=K,2=V); Q/K self-retire when init0[0]==0.
// mode 3: X2 projection (widx 4), gelu -> g_X2. (runs on side stream)
// mode 2: POST. A <- cvt(X2 + Agg). Epi: bias + residual -> dout.
// ============================================================================
__global__ void __launch_bounds__(512, 2)
k_mma(int mode, const float* __restrict__ x, const float* __restrict__ w0,
      const float* __restrict__ pre_b, const float* __restrict__ post_b,
      const float* __restrict__ m0b, const float* __restrict__ m1b,
      const float* __restrict__ m2b, const float* __restrict__ m3b,
      const float* __restrict__ r0b, const float* __restrict__ r1b,
      const float* __restrict__ r2b,
      const float* __restrict__ init0, float* __restrict__ dout, int n)
{
    extern __shared__ unsigned char sm[];
    const uint32_t sbase = smem_u32(sm);
    const uint32_t sBh = sbase + SOFF_BH, sBl = sbase + SOFF_BL;
    const uint32_t sAh = sbase + SOFF_AH, sAl = sbase + SOFF_AL;
    float* Dst = (float*)(sm + SOFF_AH);    // aliases A (A dead before staging)

    const int tid = threadIdx.x;
    const int wid = tid >> 5, lane = tid & 31;
    const int wr = wid >> 3, wc = wid & 7;
    const int tile = blockIdx.x, r0 = tile * 64;
    const int step = blockIdx.y;

    if (mode == 1 && step < 2 && __ldg(&init0[0]) == 0.0f) return;

    const int widx = (mode == 0) ? 0 : (mode == 2) ? 5 : (mode == 3) ? 4 : (step + 1);
    const int useAimg = (mode == 1 || mode == 3);

    if (mode == 0) {
        // ---- in-kernel conversion: A from x, B from w0 ----
#pragma unroll
        for (int it = 0; it < 2; it++) {
            int c = tid + it * 512;
            int row = c >> 4, kc = c & 15;
            int gr = r0 + row;
            float v[8];
            if (gr < n) {
                float4 a = *(const float4*)&x[gr * WIDTH + kc * 8];
                float4 b = *(const float4*)&x[gr * WIDTH + kc * 8 + 4];
                v[0] = a.x; v[1] = a.y; v[2] = a.z; v[3] = a.w;
                v[4] = b.x; v[5] = b.y; v[6] = b.z; v[7] = b.w;
            } else {
#pragma unroll
                for (int j = 0; j < 8; j++) v[j] = 0.0f;
            }
            __nv_bfloat16 h8[8], l8[8];
#pragma unroll
            for (int j = 0; j < 8; j++) {
                h8[j] = __float2bfloat16(v[j]);
                l8[j] = __float2bfloat16(v[j] - __bfloat162float(h8[j]));
            }
            int off = soff(row, kc);
            *(uint4*)(sm + SOFF_AH + off) = *(uint4*)h8;
            *(uint4*)(sm + SOFF_AL + off) = *(uint4*)l8;
        }
        // B: Bimg[n][k] = w0[k][n], coalesced over n for each j
#pragma unroll
        for (int it = 0; it < 4; it++) {
            int c = tid + it * 512;            // 0..2047
            int kc = c >> 7, nrow = c & 127;
            __nv_bfloat16 h8[8], l8[8];
#pragma unroll
            for (int j = 0; j < 8; j++) {
                float v = __ldg(&w0[(kc * 8 + j) * WIDTH + nrow]);
                h8[j] = __float2bfloat16(v);
                l8[j] = __float2bfloat16(v - __bfloat162float(h8[j]));
            }
            int off = soff(nrow, kc);
            *(uint4*)(sm + SOFF_BH + off) = *(uint4*)h8;
            *(uint4*)(sm + SOFF_BL + off) = *(uint4*)l8;
        }
    } else {
        // group0: B hi (+ A hi from images)
#pragma unroll
        for (int i = 0; i < 4; i++) {
            int idx = tid + i * 512;
            cpa16(sBh + idx * 16, g_iW[widx][0] + idx * 16);
        }
        const unsigned char* aimg  = g_iXh + (tile >> 1) * TILEB + (tile & 1) * ATILE;
        const unsigned char* aimgl = g_iXl + (tile >> 1) * TILEB + (tile & 1) * ATILE;
        if (useAimg) {
#pragma unroll
            for (int i = 0; i < 2; i++) {
                int idx = tid + i * 512;
                cpa16(sAh + idx * 16, aimg + idx * 16);
            }
        }
        asm volatile("cp.async.commit_group;");
        // group1: B lo (+ A lo)
#pragma unroll
        for (int i = 0; i < 4; i++) {
            int idx = tid + i * 512;
            cpa16(sBl + idx * 16, g_iW[widx][1] + idx * 16);
        }
        if (useAimg) {
#pragma unroll
            for (int i = 0; i < 2; i++) {
                int idx = tid + i * 512;
                cpa16(sAl + idx * 16, aimgl + idx * 16);
            }
        } else {
            // mode 2: A = X2 + Agg (fp32 -> hi/lo)
#pragma unroll
            for (int it = 0; it < 2; it++) {
                int c = tid + it * 512;
                int row = c >> 4, kc = c & 15;
                int gr = r0 + row;
                float v[8];
                if (gr < n) {
                    float4 a = *(const float4*)&g_X2[gr * WIDTH + kc * 8];
                    float4 b = *(const float4*)&g_X2[gr * WIDTH + kc * 8 + 4];
                    float4 c0 = *(const float4*)&g_Agg[gr * WIDTH + kc * 8];
                    float4 c1 = *(const float4*)&g_Agg[gr * WIDTH + kc * 8 + 4];
                    v[0] = a.x + c0.x; v[1] = a.y + c0.y; v[2] = a.z + c0.z; v[3] = a.w + c0.w;
                    v[4] = b.x + c1.x; v[5] = b.y + c1.y; v[6] = b.z + c1.z; v[7] = b.w + c1.w;
                } else {
#pragma unroll
                    for (int j = 0; j < 8; j++) v[j] = 0.0f;
                }
                __nv_bfloat16 h8[8], l8[8];
#pragma unroll
                for (int j = 0; j < 8; j++) {
                    h8[j] = __float2bfloat16(v[j]);
                    l8[j] = __float2bfloat16(v[j] - __bfloat162float(h8[j]));
                }
                int off = soff(row, kc);
                *(uint4*)(sm + SOFF_AH + off) = *(uint4*)h8;
                *(uint4*)(sm + SOFF_AL + off) = *(uint4*)l8;
            }
        }
        asm volatile("cp.async.commit_group;");
        asm volatile("cp.async.wait_group 1;");
    }
    __syncthreads();

    float acc[2][2][4];
#pragma unroll
    for (int i = 0; i < 2; i++)
#pragma unroll
        for (int j = 0; j < 2; j++)
#pragma unroll
            for (int q = 0; q < 4; q++) acc[i][j][q] = 0.0f;

#pragma unroll
    for (int pass = 0; pass < 3; pass++) {
        if (pass == 1 && mode != 0) {
            asm volatile("cp.async.wait_group 0;");
            __syncthreads();
        }
        uint32_t Ab = (pass == 2) ? sAl : sAh;
        uint32_t Bb = (pass == 1) ? sBl : sBh;
#pragma unroll
        for (int kk = 0; kk < 8; kk++) {
            uint32_t a[2][4], b[4];
#pragma unroll
            for (int mt = 0; mt < 2; mt++) {
                int row = wr * 32 + mt * 16 + (lane & 15);
                int kc = 2 * kk + (lane >> 4);
                ldm4(a[mt], Ab + soff(row, kc));
            }
            {
                int nn = wc * 16 + (lane & 7) + ((lane >> 4) << 3);
                int kc = 2 * kk + ((lane >> 3) & 1);
                ldm4(b, Bb + soff(nn, kc));
            }
#pragma unroll
            for (int mt = 0; mt < 2; mt++) {
                mma16816(acc[mt][0], a[mt], b[0], b[1]);
                mma16816(acc[mt][1], a[mt], b[2], b[3]);
            }
        }
    }
    __syncthreads();   // A dead -> Dst may overwrite

    // ---- stage fragments ----
#pragma unroll
    for (int mt = 0; mt < 2; mt++)
#pragma unroll
        for (int jn = 0; jn < 2; jn++) {
            int row = wr * 32 + mt * 16 + (lane >> 2);
            int col = wc * 16 + jn * 8 + 2 * (lane & 3);
            Dst[row * DSTRIDE + col]           = acc[mt][jn][0];
            Dst[row * DSTRIDE + col + 1]       = acc[mt][jn][1];
            Dst[(row + 8) * DSTRIDE + col]     = acc[mt][jn][2];
            Dst[(row + 8) * DSTRIDE + col + 1] = acc[mt][jn][3];
        }
    __syncthreads();

    if (mode == 0) {
        float4 bb = __ldg((const float4*)&pre_b[lane * 4]);
#pragma unroll
        for (int r = 0; r < 4; r++) {
            int row = wid * 4 + r;
            float4 v = *(float4*)&Dst[row * DSTRIDE + lane * 4];
            v.x += bb.x; v.y += bb.y; v.z += bb.z; v.w += bb.w;
            float s1 = v.x + v.y + v.z + v.w;
            float s2 = v.x * v.x + v.y * v.y + v.z * v.z + v.w * v.w;
#pragma unroll
            for (int m = 16; m; m >>= 1) {
                s1 += __shfl_xor_sync(0xffffffffu, s1, m);
                s2 += __shfl_xor_sync(0xffffffffu, s2, m);
            }
            float mean = s1 * (1.0f / 128.0f);
            float var  = s2 * (1.0f / 128.0f) - mean * mean;
            float rstd = rsqrtf(var + 1e-5f);
            float4 o = make_float4((v.x - mean) * rstd, (v.y - mean) * rstd,
                                   (v.z - mean) * rstd, (v.w - mean) * rstd);
            *(float4*)&Dst[row * DSTRIDE + lane * 4] = o;
        }
        __syncthreads();
        unsigned char* oh = g_iXh + (tile >> 1) * TILEB + (tile & 1) * ATILE;
        unsigned char* ol = g_iXl + (tile >> 1) * TILEB + (tile & 1) * ATILE;
#pragma unroll
        for (int it = 0; it < 2; it++) {
            int c = tid + it * 512;
            int row = c >> 4, kc = c & 15;
            float4 a = *(float4*)&Dst[row * DSTRIDE + kc * 8];
            float4 b = *(float4*)&Dst[row * DSTRIDE + kc * 8 + 4];
            float v[8] = {a.x, a.y, a.z, a.w, b.x, b.y, b.z, b.w};
            __nv_bfloat16 h8[8], l8[8];
#pragma unroll
            for (int j = 0; j < 8; j++) {
                h8[j] = __float2bfloat16(v[j]);
                l8[j] = __float2bfloat16(v[j] - __bfloat162float(h8[j]));
            }
            int off = soff(row, kc);
            *(uint4*)(oh + off) = *(uint4*)h8;
            *(uint4*)(ol + off) = *(uint4*)l8;
        }
    } else if (mode == 2) {
        float4 bb = __ldg((const float4*)&post_b[lane * 4]);
#pragma unroll
        for (int r = 0; r < 4; r++) {
            int row = wid * 4 + r;
            int gr = r0 + row;
            if (gr >= n) continue;
            float4 v = *(float4*)&Dst[row * DSTRIDE + lane * 4];
            float4 xv = __ldg((const float4*)&x[gr * WIDTH + lane * 4]);
            float4 o = make_float4(v.x + bb.x + xv.x, v.y + bb.y + xv.y,
                                   v.z + bb.z + xv.z, v.w + bb.w + xv.w);
            *(float4*)&dout[gr * WIDTH + lane * 4] = o;
        }
    } else if (mode == 3) {
        float4 bb = __ldg((const float4*)&m0b[lane * 4]);
#pragma unroll
        for (int r = 0; r < 4; r++) {
            int row = wid * 4 + r;
            int gr = r0 + row;
            if (gr >= n) continue;
            float4 v = *(float4*)&Dst[row * DSTRIDE + lane * 4];
            v.x = gelu1(v.x + bb.x); v.y = gelu1(v.y + bb.y);
            v.z = gelu1(v.z + bb.z); v.w = gelu1(v.w + bb.w);
            *(float4*)&g_X2[gr * WIDTH + lane * 4] = v;
        }
    } else {
        const float* b1; const float* b2; float sc;
        float sc_e = expf(__ldg(&init0[2]));
        float sc_v = expf(__ldg(&init0[3]));
        if (step == 0)      { b1 = m1b; b2 = r0b; sc = sc_e; }
        else if (step == 1) { b1 = m2b; b2 = r1b; sc = sc_e; }
        else                { b1 = m3b; b2 = r2b; sc = sc_v; }
        float4 bb = __ldg((const float4*)&b1[lane * 4]);
        float4 b2v = __ldg((const float4*)&b2[lane * 4]);
        bb.x += sc * b2v.x; bb.y += sc * b2v.y;
        bb.z += sc * b2v.z; bb.w += sc * b2v.w;
#pragma unroll
        for (int r = 0; r < 4; r++) {
            int row = wid * 4 + r;
            int gr = r0 + row;
            if (gr >= n) continue;
            float4 v = *(float4*)&Dst[row * DSTRIDE + lane * 4];
            v.x += bb.x; v.y += bb.y; v.z += bb.z; v.w += bb.w;
            if (step == 0) {
                *(float4*)&g_Q[gr * WIDTH + lane * 4] = v;
            } else if (step == 1) {
                *(float4*)&g_K[gr * WIDTH + lane * 4] = v;
            } else {
                __half h4[4] = {__float2half_rn(v.x), __float2half_rn(v.y),
                                __float2half_rn(v.z), __float2half_rn(v.w)};
                *(uint2*)&g_Vh[gr * WIDTH + lane * 4] = *(uint2*)h4;
            }
        }
    }
}

// ============================================================================
// Edge phase: warp per destination node (CSR), 512 threads, fast unroll x4.
// Writes g_Agg[v] (zeros when no in-edges) -- independent of g_X2.
// ============================================================================
__global__ void __launch_bounds__(512) k_edgec(const float* __restrict__ init0, int n)
{
    int v = blockIdx.x * 16 + (threadIdx.x >> 5);
    if (v >= n) return;
    int lane = threadIdx.x & 31;
    int b0 = g_base[v], b1 = g_base[v + 1];
    int c4 = lane << 2;
    float4 acc = make_float4(0.f, 0.f, 0.f, 0.f);

    float a0 = __ldg(&init0[0]);
    float bc = __ldg(&init0[1]);

    if (b0 < b1) {
        if (a0 == 0.0f) {
            int j = b0;
            for (; j + 4 <= b1; j += 4) {
                int s0 = __ldg(&g_esrc[j]),   s1 = __ldg(&g_esrc[j+1]);
                int s2 = __ldg(&g_esrc[j+2]), s3 = __ldg(&g_esrc[j+3]);
                int i0 = __ldg(&g_eidx[j]),   i1 = __ldg(&g_eidx[j+1]);
                int i2 = __ldg(&g_eidx[j+2]), i3 = __ldg(&g_eidx[j+3]);
                uint2 v0 = __ldg((const uint2*)&g_Vh[s0 * WIDTH + c4]);
                uint2 v1 = __ldg((const uint2*)&g_Vh[s1 * WIDTH + c4]);
                uint2 v2 = __ldg((const uint2*)&g_Vh[s2 * WIDTH + c4]);
                uint2 v3 = __ldg((const uint2*)&g_Vh[s3 * WIDTH + c4]);
                uint2 t0 = __ldg((const uint2*)&g_T2h[i0 * WIDTH + c4]);
                uint2 t1 = __ldg((const uint2*)&g_T2h[i1 * WIDTH + c4]);
                uint2 t2 = __ldg((const uint2*)&g_T2h[i2 * WIDTH + c4]);
                uint2 t3 = __ldg((const uint2*)&g_T2h[i3 * WIDTH + c4]);
#pragma unroll
                for (int u = 0; u < 4; u++) {
                    uint2 vr = (u == 0) ? v0 : (u == 1) ? v1 : (u == 2) ? v2 : v3;
                    uint2 tr = (u == 0) ? t0 : (u == 1) ? t1 : (u == 2) ? t2 : t3;
                    float2 a_ = __half22float2(*(const __half2*)&vr.x);
                    float2 b_ = __half22float2(*(const __half2*)&vr.y);
                    float2 ta = __half22float2(*(const __half2*)&tr.x);
                    float2 tb = __half22float2(*(const __half2*)&tr.y);
                    acc.x += gelu_t(a_.x + ta.x); acc.y += gelu_t(a_.y + ta.y);
                    acc.z += gelu_t(b_.x + tb.x); acc.w += gelu_t(b_.y + tb.y);
                }
            }
            for (; j < b1; j++) {
                int s0 = __ldg(&g_esrc[j]);
                int i0 = __ldg(&g_eidx[j]);
                uint2 vr = __ldg((const uint2*)&g_Vh[s0 * WIDTH + c4]);
                uint2 tr = __ldg((const uint2*)&g_T2h[i0 * WIDTH + c4]);
                float2 a_ = __half22float2(*(const __half2*)&vr.x);
                float2 b_ = __half22float2(*(const __half2*)&vr.y);
                float2 ta = __half22float2(*(const __half2*)&tr.x);
                float2 tb = __half22float2(*(const __half2*)&tr.y);
                acc.x += gelu_t(a_.x + ta.x); acc.y += gelu_t(a_.y + ta.y);
                acc.z += gelu_t(b_.x + tb.x); acc.w += gelu_t(b_.y + tb.y);
            }
            float att = __expf(bc);
            acc.x *= att; acc.y *= att; acc.z *= att; acc.w *= att;
        } else {
            const float4* T = (const float4*)g_T81;
            float4 Qv = *(const float4*)&g_Q[v * WIDTH + c4];
            float sA = a0 * 0.125f;
            for (int j = b0; j < b1; j++) {
                int src = __ldg(&g_esrc[j]);
                int idx = __ldg(&g_eidx[j]);
                float4 t0 = __ldg(&T[(idx * 3 + 0) * 32 + lane]);
                float4 t1 = __ldg(&T[(idx * 3 + 1) * 32 + lane]);
                float4 kv = __ldg((const float4*)&g_K[src * WIDTH + c4]);
                uint2 vr = __ldg((const uint2*)&g_Vh[src * WIDTH + c4]);
                uint2 tr = __ldg((const uint2*)&g_T2h[idx * WIDTH + c4]);
                float2 vlo = __half22float2(*(const __half2*)&vr.x);
                float2 vhi = __half22float2(*(const __half2*)&vr.y);
                float2 ta = __half22float2(*(const __half2*)&tr.x);
                float2 tb = __half22float2(*(const __half2*)&tr.y);
                float s = (Qv.x + t0.x) * (kv.x + t1.x) + (Qv.y + t0.y) * (kv.y + t1.y)
                        + (Qv.z + t0.z) * (kv.z + t1.z) + (Qv.w + t0.w) * (kv.w + t1.w);
#pragma unroll
                for (int m = 8; m; m >>= 1) s += __shfl_xor_sync(0xffffffffu, s, m);
                float att = __expf(fmaf(s, sA, bc));
                acc.x = fmaf(gelu_t(vlo.x + ta.x), att, acc.x);
                acc.y = fmaf(gelu_t(vlo.y + ta.y), att, acc.y);
                acc.z = fmaf(gelu_t(vhi.x + tb.x), att, acc.z);
                acc.w = fmaf(gelu_t(vhi.y + tb.y), att, acc.w);
            }
        }
    }
    *(float4*)&g_Agg[v * WIDTH + c4] = acc;
}

extern "C" void kernel_launch(void* const* d_in, const int* in_sizes, int n_in,
                              void* d_out, int out_size)
{
    const float* x        = (const float*)d_in[0];
    const int*   ei       = (const int*)  d_in[1];
    const int*   ea       = (const int*)  d_in[2];
    const float* pre_w    = (const float*)d_in[3];
    const float* pre_b    = (const float*)d_in[4];
    const float* msg0_w   = (const float*)d_in[5];
    const float* msg0_b   = (const float*)d_in[6];
    const float* msg1_w   = (const float*)d_in[7];
    const float* msg1_b   = (const float*)d_in[8];
    const float* msg2_w   = (const float*)d_in[9];
    const float* msg2_b   = (const float*)d_in[10];
    const float* msg3_w   = (const float*)d_in[11];
    const float* msg3_b   = (const float*)d_in[12];
    const float* remix0_w = (const float*)d_in[13];
    const float* remix0_b = (const float*)d_in[14];
    const float* remix1_w = (const float*)d_in[15];
    const float* remix1_b = (const float*)d_in[16];
    const float* remix2_w = (const float*)d_in[17];
    const float* remix2_b = (const float*)d_in[18];
    const float* post_w   = (const float*)d_in[19];
    const float* post_b   = (const float*)d_in[20];
    const float* emb0     = (const float*)d_in[21];
    const float* emb1     = (const float*)d_in[22];
    const float* emb2     = (const float*)d_in[23];
    const float* emb3     = (const float*)d_in[24];
    const float* einit    = (const float*)d_in[25];
    const float* init0    = (const float*)d_in[26];

    int n = in_sizes[0] / WIDTH;
    int e = in_sizes[1] / 2;
    int nt = (n + 63) / 64;

    static cudaStream_t s2 = 0, s3 = 0;
    static cudaEvent_t ev0 = 0, evW = 0, evCSR = 0, evPRE = 0, ev3 = 0;
    if (!s2) {
        cudaFuncSetAttribute(k_mma, cudaFuncAttributeMaxDynamicSharedMemorySize, DSMEM);
        cudaStreamCreateWithFlags(&s2, cudaStreamNonBlocking);
        cudaStreamCreateWithFlags(&s3, cudaStreamNonBlocking);
        cudaEventCreateWithFlags(&ev0, cudaEventDisableTiming);
        cudaEventCreateWithFlags(&evW, cudaEventDisableTiming);
        cudaEventCreateWithFlags(&evCSR, cudaEventDisableTiming);
        cudaEventCreateWithFlags(&evPRE, cudaEventDisableTiming);
        cudaEventCreateWithFlags(&ev3, cudaEventDisableTiming);
    }

    // fork side stream s2: weight images 1..5, tables, CSR build
    cudaEventRecord(ev0, 0);
    cudaStreamWaitEvent(s2, ev0, 0);

    k_prepw<<<40, 256, 0, s2>>>(msg1_w, msg2_w, msg3_w, msg0_w, post_w);
    cudaEventRecord(evW, s2);
    dim3 tg(3, 34);
    k_tables<<<tg, 128, 0, s2>>>(remix0_w, remix1_w, remix2_w,
                                 emb0, emb1, emb2, emb3, einit, init0);
    dim3 cg(3, 81);
    k_combine<<<cg, 128, 0, s2>>>();
    k_zero<<<(n + 255) / 256, 256, 0, s2>>>(n);
    k_hist<<<512, 256, 0, s2>>>(ei, e);
    k_scan<<<1, 1024, 0, s2>>>(n, e);
    k_scatter<<<512, 256, 0, s2>>>(ei, ea, e);
    cudaEventRecord(evCSR, s2);

    // main: PRE (in-kernel w0 conversion, no prep dependency)
    k_mma<<<nt, 512, DSMEM>>>(0, x, pre_w, pre_b, post_b, msg0_b, msg1_b,
                              msg2_b, msg3_b, remix0_b, remix1_b, remix2_b,
                              init0, (float*)d_out, n);
    cudaEventRecord(evPRE, 0);

    // s3: X2 projection, overlaps QKV + edge
    cudaStreamWaitEvent(s3, evPRE, 0);
    cudaStreamWaitEvent(s3, evW, 0);
    k_mma<<<nt, 512, DSMEM, s3>>>(3, x, pre_w, pre_b, post_b, msg0_b, msg1_b,
                                  msg2_b, msg3_b, remix0_b, remix1_b, remix2_b,
                                  init0, (float*)d_out, n);
    cudaEventRecord(ev3, s3);

    // main: Q,K,V projections (Q/K self-retire on fast path)
    cudaStreamWaitEvent(0, evW, 0);
    dim3 qg(nt, 3);
    k_mma<<<qg, 512, DSMEM>>>(1, x, pre_w, pre_b, post_b, msg0_b, msg1_b,
                              msg2_b, msg3_b, remix0_b, remix1_b, remix2_b,
                              init0, (float*)d_out, n);

    // edge phase (needs V + tables + CSR; independent of X2)
    cudaStreamWaitEvent(0, evCSR, 0);
    k_edgec<<<(n + 15) / 16, 512>>>(init0, n);

    // POST: out = x + (X2 + Agg) @ post_w + post_b
    cudaStreamWaitEvent(0, ev3, 0);
    k_mma<<<nt, 512, DSMEM>>>(2, x, pre_w, pre_b, post_b, msg0_b, msg1_b,
                              msg2_b, msg3_b, remix0_b, remix1_b, remix2_b,
                              init0, (float*)d_out, n);
}

// round 14
// speedup vs baseline: 1.4296x; 1.4296x over previous
#include <cuda_runtime.h>
#include <cuda_bf16.h>
#include <cuda_fp16.h>
#include <math.h>
#include <stdint.h>

#define WIDTH 128
#define NMAX  50176
#define EMAX  512000
#define TILEB 32768                 // full 128x128 bf16 image tile
#define ATILE 16384                 // 64-row half tile
#define DSTRIDE 132
// smem: Bh[32K] Bl[32K] | union( Ah[16K] Al[16K] , Dst[33792] )
#define SOFF_BH 0
#define SOFF_BL 32768
#define SOFF_AH 65536
#define SOFF_AL 81920
#define DSMEM   99328

// ---- scratch (device globals) ----
__device__ float  g_Q  [NMAX * WIDTH];
__device__ float  g_K  [NMAX * WIDTH];
__device__ __half g_Vh [NMAX * WIDTH];
__device__ float  g_X2 [NMAX * WIDTH];
__device__ float  g_Agg[NMAX * WIDTH];
__device__ float  g_T  [3 * 34 * WIDTH];
__device__ float  g_T81[81 * 3 * WIDTH];
__device__ __half g_T2h[81 * WIDTH];
__device__ unsigned char g_iW[6][2][TILEB];
__device__ unsigned char g_iXh[392 * TILEB];
__device__ unsigned char g_iXl[392 * TILEB];
__device__ int g_cnt [NMAX];
__device__ int g_cur [NMAX];
__device__ int g_base[NMAX + 1];
__device__ int g_esrc[EMAX];
__device__ int g_eidx[EMAX];

__device__ __forceinline__ float gelu1(float x) {
    return 0.5f * x * (1.0f + erff(x * 0.7071067811865475f));
}
__device__ __forceinline__ float gelu_t(float x) {
    float u = 0.7978845608028654f * fmaf(0.044715f * x, x * x, x);
    float t;
    asm("tanh.approx.f32 %0, %1;" : "=f"(t) : "f"(u));
    return 0.5f * x * (1.0f + t);
}
__device__ __forceinline__ int soff(int row, int kc) {
    return row * 256 + ((kc ^ (row & 7)) << 4);
}
__device__ __forceinline__ uint32_t smem_u32(const void* p) {
    uint32_t a;
    asm("{ .reg .u64 t; cvta.to.shared.u64 t, %1; cvt.u32.u64 %0, t; }" : "=r"(a) : "l"(p));
    return a;
}
__device__ __forceinline__ void cpa16(uint32_t s, const void* g) {
    asm volatile("cp.async.ca.shared.global [%0], [%1], 16;" :: "r"(s), "l"(g));
}
__device__ __forceinline__ void ldm4(uint32_t* r, uint32_t a) {
    asm volatile("ldmatrix.sync.aligned.m8n8.x4.shared.b16 {%0,%1,%2,%3}, [%4];"
                 : "=r"(r[0]), "=r"(r[1]), "=r"(r[2]), "=r"(r[3]) : "r"(a));
}
__device__ __forceinline__ void mma16816(float* c, const uint32_t* a, uint32_t b0, uint32_t b1) {
    asm volatile(
        "mma.sync.aligned.m16n8k16.row.col.f32.bf16.bf16.f32 "
        "{%0,%1,%2,%3}, {%4,%5,%6,%7}, {%8,%9}, {%0,%1,%2,%3};"
        : "+f"(c[0]), "+f"(c[1]), "+f"(c[2]), "+f"(c[3])
        : "r"(a[0]), "r"(a[1]), "r"(a[2]), "r"(a[3]), "r"(b0), "r"(b1));
}

// ============================================================================
// Tables
// ============================================================================
__global__ void k_tables(const float* __restrict__ r0w, const float* __restrict__ r1w,
                         const float* __restrict__ r2w,
                         const float* __restrict__ e0, const float* __restrict__ e1,
                         const float* __restrict__ e2, const float* __restrict__ e3,
                         const float* __restrict__ einit, const float* __restrict__ init0)
{
    int j = blockIdx.x, r = blockIdx.y, o = threadIdx.x;
    int c, lr;
    if (r < 6)       { c = 0; lr = r; }
    else if (r < 13) { c = 1; lr = r - 6; }
    else if (r < 16) { c = 2; lr = r - 13; }
    else             { c = 3; lr = r - 16; }
    const float* emb = (c == 0) ? e0 : (c == 1) ? e1 : (c == 2) ? e2 : e3;
    const float* rw  = (j == 0) ? r0w : (j == 1) ? r1w : r2w;

    __shared__ float er[64];
    if (o < 64) er[o] = emb[lr * 64 + o];
    __syncthreads();

    float s = 0.0f;
#pragma unroll
    for (int m = 0; m < 64; m++) s += er[m] * rw[m * WIDTH + o];

    float es = expf(einit[0]) + expf(einit[1]) + expf(einit[2]) + expf(einit[3]);
    float xw = expf(einit[c]) * rsqrtf(es);
    float sf = expf((j == 2) ? init0[3] : init0[2]);
    g_T[(j * 34 + r) * WIDTH + o] = s * xw * sf;
}

__global__ void k_combine()
{
    int j = blockIdx.x, i = blockIdx.y, o = threadIdx.x;
    int d0 = i % 3, d1 = (i / 3) % 3, d2 = (i / 9) % 3, d3 = i / 27;
    float v = g_T[(j * 34 + d0) * WIDTH + o] + g_T[(j * 34 + 6 + d1) * WIDTH + o]
            + g_T[(j * 34 + 13 + d2) * WIDTH + o] + g_T[(j * 34 + 16 + d3) * WIDTH + o];
    g_T81[(i * 3 + j) * WIDTH + o] = v;
    if (j == 2) g_T2h[i * WIDTH + o] = __float2half(v);
}

// ============================================================================
// CSR build
// ============================================================================
__global__ void k_zero(int n)
{
    int i = blockIdx.x * blockDim.x + threadIdx.x;
    if (i < n) { g_cnt[i] = 0; g_cur[i] = 0; }
}
__global__ void k_hist(const int* __restrict__ ei, int e)
{
    for (int i = blockIdx.x * blockDim.x + threadIdx.x; i < e; i += gridDim.x * blockDim.x)
        atomicAdd(&g_cnt[ei[e + i]], 1);
}
__global__ void __launch_bounds__(1024) k_scan(int n, int e)
{
    __shared__ int sp[1024];
    int t = threadIdx.x;
    int chunk = (n + 1023) >> 10;
    int lo = t * chunk, hi = min(lo + chunk, n);
    int s = 0;
    for (int i = lo; i < hi; i++) s += g_cnt[i];
    sp[t] = s;
    __syncthreads();
    for (int d = 1; d < 1024; d <<= 1) {
        int v = (t >= d) ? sp[t - d] : 0;
        __syncthreads();
        if (t >= d) sp[t] += v;
        __syncthreads();
    }
    int run = (t > 0) ? sp[t - 1] : 0;
    for (int i = lo; i < hi; i++) { int c = g_cnt[i]; g_base[i] = run; run += c; }
    if (t == 0) g_base[n] = e;
}
__global__ void k_scatter(const int* __restrict__ ei, const int* __restrict__ ea, int e)
{
    for (int i = blockIdx.x * blockDim.x + threadIdx.x; i < e; i += gridDim.x * blockDim.x) {
        int dst = ei[e + i];
        int4 a = __ldg((const int4*)ea + i);
        int idx = a.x + 3 * a.y + 9 * a.z + 27 * a.w;
        int pos = g_base[dst] + atomicAdd(&g_cur[dst], 1);
        g_esrc[pos] = ei[i];
        g_eidx[pos] = idx;
    }
}

// ============================================================================
// Weight prep: wi = first + blockIdx.x/8
// ============================================================================
__global__ void __launch_bounds__(256) k_prepw(const float* __restrict__ w0,
    const float* __restrict__ w1, const float* __restrict__ w2,
    const float* __restrict__ w3, const float* __restrict__ w4,
    const float* __restrict__ w5, int first)
{
    int wi = first + (blockIdx.x >> 3), sl = blockIdx.x & 7;
    const float* W = (wi == 0) ? w0 : (wi == 1) ? w1 : (wi == 2) ? w2
                   : (wi == 3) ? w3 : (wi == 4) ? w4 : w5;
    int nrow = sl * 16 + (threadIdx.x >> 4);
    int kc = threadIdx.x & 15;
    __nv_bfloat16 h8[8], l8[8];
#pragma unroll
    for (int j = 0; j < 8; j++) {
        float v = W[(kc * 8 + j) * WIDTH + nrow];
        h8[j] = __float2bfloat16(v);
        l8[j] = __float2bfloat16(v - __bfloat162float(h8[j]));
    }
    int off = soff(nrow, kc);
    *(uint4*)(g_iW[wi][0] + off) = *(uint4*)h8;
    *(uint4*)(g_iW[wi][1] + off) = *(uint4*)l8;
}

// ============================================================================
// mma.sync GEMM: 64x128 tile, 512 thr (2x8 warps, 32x16/warp), 2 CTAs/SM.
// bf16 hi/lo 3-pass, pipelined cp.async (group0 = hi, group1 = lo).
// mode 0: PRE -> xx half-images (A from x).
// mode 1: blockIdx.y = step (0=Q,1=K,2=V); Q/K self-retire when init0[0]==0.
// mode 3: X2 projection (widx 4), A from images, gelu -> g_X2.  (side stream)
// mode 2: POST. A <- cvt(X2 + Agg). Epi: bias + residual -> dout.
// ============================================================================
__global__ void __launch_bounds__(512, 2)
k_mma(int mode, const float* __restrict__ x,
      const float* __restrict__ pre_b, const float* __restrict__ post_b,
      const float* __restrict__ m0b, const float* __restrict__ m1b,
      const float* __restrict__ m2b, const float* __restrict__ m3b,
      const float* __restrict__ r0b, const float* __restrict__ r1b,
      const float* __restrict__ r2b,
      const float* __restrict__ init0, float* __restrict__ dout, int n)
{
    extern __shared__ unsigned char sm[];
    const uint32_t sbase = smem_u32(sm);
    const uint32_t sBh = sbase + SOFF_BH, sBl = sbase + SOFF_BL;
    const uint32_t sAh = sbase + SOFF_AH, sAl = sbase + SOFF_AL;
    float* Dst = (float*)(sm + SOFF_AH);    // aliases A (A dead before staging)

    const int tid = threadIdx.x;
    const int wid = tid >> 5, lane = tid & 31;
    const int wr = wid >> 3, wc = wid & 7;      // 2 x 8 warp grid
    const int tile = blockIdx.x, r0 = tile * 64;
    const int step = blockIdx.y;

    if (mode == 1 && step < 2 && __ldg(&init0[0]) == 0.0f) return;

    const int widx = (mode == 0) ? 0 : (mode == 2) ? 5 : (mode == 3) ? 4 : (step + 1);
    const int useAimg = (mode == 1 || mode == 3);

    // group0: B hi (+ A hi for image modes)
#pragma unroll
    for (int i = 0; i < 4; i++) {
        int idx = tid + i * 512;
        cpa16(sBh + idx * 16, g_iW[widx][0] + idx * 16);
    }
    const unsigned char* aimg  = g_iXh + (tile >> 1) * TILEB + (tile & 1) * ATILE;
    const unsigned char* aimgl = g_iXl + (tile >> 1) * TILEB + (tile & 1) * ATILE;
    if (useAimg) {
#pragma unroll
        for (int i = 0; i < 2; i++) {
            int idx = tid + i * 512;
            cpa16(sAh + idx * 16, aimg + idx * 16);
        }
    }
    asm volatile("cp.async.commit_group;");
    // group1: B lo (+ A lo)
#pragma unroll
    for (int i = 0; i < 4; i++) {
        int idx = tid + i * 512;
        cpa16(sBl + idx * 16, g_iW[widx][1] + idx * 16);
    }
    if (useAimg) {
#pragma unroll
        for (int i = 0; i < 2; i++) {
            int idx = tid + i * 512;
            cpa16(sAl + idx * 16, aimgl + idx * 16);
        }
    } else {
        // convert A from fp32 source: mode 0 -> x, mode 2 -> X2 + Agg
#pragma unroll
        for (int it = 0; it < 2; it++) {
            int c = tid + it * 512;
            int row = c >> 4, kc = c & 15;
            int gr = r0 + row;
            float v[8];
            if (gr < n) {
                if (mode == 0) {
                    float4 a = *(const float4*)&x[gr * WIDTH + kc * 8];
                    float4 b = *(const float4*)&x[gr * WIDTH + kc * 8 + 4];
                    v[0] = a.x; v[1] = a.y; v[2] = a.z; v[3] = a.w;
                    v[4] = b.x; v[5] = b.y; v[6] = b.z; v[7] = b.w;
                } else {
                    float4 a = *(const float4*)&g_X2[gr * WIDTH + kc * 8];
                    float4 b = *(const float4*)&g_X2[gr * WIDTH + kc * 8 + 4];
                    float4 c0 = *(const float4*)&g_Agg[gr * WIDTH + kc * 8];
                    float4 c1 = *(const float4*)&g_Agg[gr * WIDTH + kc * 8 + 4];
                    v[0] = a.x + c0.x; v[1] = a.y + c0.y; v[2] = a.z + c0.z; v[3] = a.w + c0.w;
                    v[4] = b.x + c1.x; v[5] = b.y + c1.y; v[6] = b.z + c1.z; v[7] = b.w + c1.w;
                }
            } else {
#pragma unroll
                for (int j = 0; j < 8; j++) v[j] = 0.0f;
            }
            __nv_bfloat16 h8[8], l8[8];
#pragma unroll
            for (int j = 0; j < 8; j++) {
                h8[j] = __float2bfloat16(v[j]);
                l8[j] = __float2bfloat16(v[j] - __bfloat162float(h8[j]));
            }
            int off = soff(row, kc);
            *(uint4*)(sm + SOFF_AH + off) = *(uint4*)h8;
            *(uint4*)(sm + SOFF_AL + off) = *(uint4*)l8;
        }
    }
    asm volatile("cp.async.commit_group;");
    asm volatile("cp.async.wait_group 1;");     // hi halves ready
    __syncthreads();

    float acc[2][2][4];
#pragma unroll
    for (int i = 0; i < 2; i++)
#pragma unroll
        for (int j = 0; j < 2; j++)
#pragma unroll
            for (int q = 0; q < 4; q++) acc[i][j][q] = 0.0f;

#pragma unroll
    for (int pass = 0; pass < 3; pass++) {
        if (pass == 1) {
            asm volatile("cp.async.wait_group 0;");
            __syncthreads();
        }
        uint32_t Ab = (pass == 2) ? sAl : sAh;
        uint32_t Bb = (pass == 1) ? sBl : sBh;
#pragma unroll
        for (int kk = 0; kk < 8; kk++) {
            uint32_t a[2][4], b[4];
#pragma unroll
            for (int mt = 0; mt < 2; mt++) {
                int row = wr * 32 + mt * 16 + (lane & 15);
                int kc = 2 * kk + (lane >> 4);
                ldm4(a[mt], Ab + soff(row, kc));
            }
            {
                int nn = wc * 16 + (lane & 7) + ((lane >> 4) << 3);
                int kc = 2 * kk + ((lane >> 3) & 1);
                ldm4(b, Bb + soff(nn, kc));
            }
#pragma unroll
            for (int mt = 0; mt < 2; mt++) {
                mma16816(acc[mt][0], a[mt], b[0], b[1]);
                mma16816(acc[mt][1], a[mt], b[2], b[3]);
            }
        }
    }
    __syncthreads();   // A dead -> Dst may overwrite

    // ---- stage fragments ----
#pragma unroll
    for (int mt = 0; mt < 2; mt++)
#pragma unroll
        for (int jn = 0; jn < 2; jn++) {
            int row = wr * 32 + mt * 16 + (lane >> 2);
            int col = wc * 16 + jn * 8 + 2 * (lane & 3);
            Dst[row * DSTRIDE + col]           = acc[mt][jn][0];
            Dst[row * DSTRIDE + col + 1]       = acc[mt][jn][1];
            Dst[(row + 8) * DSTRIDE + col]     = acc[mt][jn][2];
            Dst[(row + 8) * DSTRIDE + col + 1] = acc[mt][jn][3];
        }
    __syncthreads();

    if (mode == 0) {
        float4 bb = __ldg((const float4*)&pre_b[lane * 4]);
#pragma unroll
        for (int r = 0; r < 4; r++) {
            int row = wid * 4 + r;
            float4 v = *(float4*)&Dst[row * DSTRIDE + lane * 4];
            v.x += bb.x; v.y += bb.y; v.z += bb.z; v.w += bb.w;
            float s1 = v.x + v.y + v.z + v.w;
            float s2 = v.x * v.x + v.y * v.y + v.z * v.z + v.w * v.w;
#pragma unroll
            for (int m = 16; m; m >>= 1) {
                s1 += __shfl_xor_sync(0xffffffffu, s1, m);
                s2 += __shfl_xor_sync(0xffffffffu, s2, m);
            }
            float mean = s1 * (1.0f / 128.0f);
            float var  = s2 * (1.0f / 128.0f) - mean * mean;
            float rstd = rsqrtf(var + 1e-5f);
            float4 o = make_float4((v.x - mean) * rstd, (v.y - mean) * rstd,
                                   (v.z - mean) * rstd, (v.w - mean) * rstd);
            *(float4*)&Dst[row * DSTRIDE + lane * 4] = o;
        }
        __syncthreads();
        unsigned char* oh = g_iXh + (tile >> 1) * TILEB + (tile & 1) * ATILE;
        unsigned char* ol = g_iXl + (tile >> 1) * TILEB + (tile & 1) * ATILE;
#pragma unroll
        for (int it = 0; it < 2; it++) {
            int c = tid + it * 512;
            int row = c >> 4, kc = c & 15;
            float4 a = *(float4*)&Dst[row * DSTRIDE + kc * 8];
            float4 b = *(float4*)&Dst[row * DSTRIDE + kc * 8 + 4];
            float v[8] = {a.x, a.y, a.z, a.w, b.x, b.y, b.z, b.w};
            __nv_bfloat16 h8[8], l8[8];
#pragma unroll
            for (int j = 0; j < 8; j++) {
                h8[j] = __float2bfloat16(v[j]);
                l8[j] = __float2bfloat16(v[j] - __bfloat162float(h8[j]));
            }
            int off = soff(row, kc);
            *(uint4*)(oh + off) = *(uint4*)h8;
            *(uint4*)(ol + off) = *(uint4*)l8;
        }
    } else if (mode == 2) {
        float4 bb = __ldg((const float4*)&post_b[lane * 4]);
#pragma unroll
        for (int r = 0; r < 4; r++) {
            int row = wid * 4 + r;
            int gr = r0 + row;
            if (gr >= n) continue;
            float4 v = *(float4*)&Dst[row * DSTRIDE + lane * 4];
            float4 xv = __ldg((const float4*)&x[gr * WIDTH + lane * 4]);
            float4 o = make_float4(v.x + bb.x + xv.x, v.y + bb.y + xv.y,
                                   v.z + bb.z + xv.z, v.w + bb.w + xv.w);
            *(float4*)&dout[gr * WIDTH + lane * 4] = o;
        }
    } else if (mode == 3) {
        float4 bb = __ldg((const float4*)&m0b[lane * 4]);
#pragma unroll
        for (int r = 0; r < 4; r++) {
            int row = wid * 4 + r;
            int gr = r0 + row;
            if (gr >= n) continue;
            float4 v = *(float4*)&Dst[row * DSTRIDE + lane * 4];
            v.x = gelu1(v.x + bb.x); v.y = gelu1(v.y + bb.y);
            v.z = gelu1(v.z + bb.z); v.w = gelu1(v.w + bb.w);
            *(float4*)&g_X2[gr * WIDTH + lane * 4] = v;
        }
    } else {
        const float* b1; const float* b2; float sc;
        float sc_e = expf(__ldg(&init0[2]));
        float sc_v = expf(__ldg(&init0[3]));
        if (step == 0)      { b1 = m1b; b2 = r0b; sc = sc_e; }
        else if (step == 1) { b1 = m2b; b2 = r1b; sc = sc_e; }
        else                { b1 = m3b; b2 = r2b; sc = sc_v; }
        float4 bb = __ldg((const float4*)&b1[lane * 4]);
        float4 b2v = __ldg((const float4*)&b2[lane * 4]);
        bb.x += sc * b2v.x; bb.y += sc * b2v.y;
        bb.z += sc * b2v.z; bb.w += sc * b2v.w;
#pragma unroll
        for (int r = 0; r < 4; r++) {
            int row = wid * 4 + r;
            int gr = r0 + row;
            if (gr >= n) continue;
            float4 v = *(float4*)&Dst[row * DSTRIDE + lane * 4];
            v.x += bb.x; v.y += bb.y; v.z += bb.z; v.w += bb.w;
            if (step == 0) {
                *(float4*)&g_Q[gr * WIDTH + lane * 4] = v;
            } else if (step == 1) {
                *(float4*)&g_K[gr * WIDTH + lane * 4] = v;
            } else {
                __half h4[4] = {__float2half_rn(v.x), __float2half_rn(v.y),
                                __float2half_rn(v.z), __float2half_rn(v.w)};
                *(uint2*)&g_Vh[gr * WIDTH + lane * 4] = *(uint2*)h4;
            }
        }
    }
}

// ============================================================================
// Edge phase: warp per destination node (CSR), 512 threads, fast unroll x4.
// Writes g_Agg[v] (zeros when no in-edges) -- independent of g_X2.
// ============================================================================
__global__ void __launch_bounds__(512) k_edgec(const float* __restrict__ init0, int n)
{
    int v = blockIdx.x * 16 + (threadIdx.x >> 5);
    if (v >= n) return;
    int lane = threadIdx.x & 31;
    int b0 = g_base[v], b1 = g_base[v + 1];
    int c4 = lane << 2;
    float4 acc = make_float4(0.f, 0.f, 0.f, 0.f);

    float a0 = __ldg(&init0[0]);
    float bc = __ldg(&init0[1]);

    if (b0 < b1) {
        if (a0 == 0.0f) {
            int j = b0;
            for (; j + 4 <= b1; j += 4) {
                int s0 = __ldg(&g_esrc[j]),   s1 = __ldg(&g_esrc[j+1]);
                int s2 = __ldg(&g_esrc[j+2]), s3 = __ldg(&g_esrc[j+3]);
                int i0 = __ldg(&g_eidx[j]),   i1 = __ldg(&g_eidx[j+1]);
                int i2 = __ldg(&g_eidx[j+2]), i3 = __ldg(&g_eidx[j+3]);
                uint2 v0 = __ldg((const uint2*)&g_Vh[s0 * WIDTH + c4]);
                uint2 v1 = __ldg((const uint2*)&g_Vh[s1 * WIDTH + c4]);
                uint2 v2 = __ldg((const uint2*)&g_Vh[s2 * WIDTH + c4]);
                uint2 v3 = __ldg((const uint2*)&g_Vh[s3 * WIDTH + c4]);
                uint2 t0 = __ldg((const uint2*)&g_T2h[i0 * WIDTH + c4]);
                uint2 t1 = __ldg((const uint2*)&g_T2h[i1 * WIDTH + c4]);
                uint2 t2 = __ldg((const uint2*)&g_T2h[i2 * WIDTH + c4]);
                uint2 t3 = __ldg((const uint2*)&g_T2h[i3 * WIDTH + c4]);
#pragma unroll
                for (int u = 0; u < 4; u++) {
                    uint2 vr = (u == 0) ? v0 : (u == 1) ? v1 : (u == 2) ? v2 : v3;
                    uint2 tr = (u == 0) ? t0 : (u == 1) ? t1 : (u == 2) ? t2 : t3;
                    float2 a_ = __half22float2(*(const __half2*)&vr.x);
                    float2 b_ = __half22float2(*(const __half2*)&vr.y);
                    float2 ta = __half22float2(*(const __half2*)&tr.x);
                    float2 tb = __half22float2(*(const __half2*)&tr.y);
                    acc.x += gelu_t(a_.x + ta.x); acc.y += gelu_t(a_.y + ta.y);
                    acc.z += gelu_t(b_.x + tb.x); acc.w += gelu_t(b_.y + tb.y);
                }
            }
            for (; j < b1; j++) {
                int s0 = __ldg(&g_esrc[j]);
                int i0 = __ldg(&g_eidx[j]);
                uint2 vr = __ldg((const uint2*)&g_Vh[s0 * WIDTH + c4]);
                uint2 tr = __ldg((const uint2*)&g_T2h[i0 * WIDTH + c4]);
                float2 a_ = __half22float2(*(const __half2*)&vr.x);
                float2 b_ = __half22float2(*(const __half2*)&vr.y);
                float2 ta = __half22float2(*(const __half2*)&tr.x);
                float2 tb = __half22float2(*(const __half2*)&tr.y);
                acc.x += gelu_t(a_.x + ta.x); acc.y += gelu_t(a_.y + ta.y);
                acc.z += gelu_t(b_.x + tb.x); acc.w += gelu_t(b_.y + tb.y);
            }
            float att = __expf(bc);
            acc.x *= att; acc.y *= att; acc.z *= att; acc.w *= att;
        } else {
            const float4* T = (const float4*)g_T81;
            float4 Qv = *(const float4*)&g_Q[v * WIDTH + c4];
            float sA = a0 * 0.125f;
            for (int j = b0; j < b1; j++) {
                int src = __ldg(&g_esrc[j]);
                int idx = __ldg(&g_eidx[j]);
                float4 t0 = __ldg(&T[(idx * 3 + 0) * 32 + lane]);
                float4 t1 = __ldg(&T[(idx * 3 + 1) * 32 + lane]);
                float4 kv = __ldg((const float4*)&g_K[src * WIDTH + c4]);
                uint2 vr = __ldg((const uint2*)&g_Vh[src * WIDTH + c4]);
                uint2 tr = __ldg((const uint2*)&g_T2h[idx * WIDTH + c4]);
                float2 vlo = __half22float2(*(const __half2*)&vr.x);
                float2 vhi = __half22float2(*(const __half2*)&vr.y);
                float2 ta = __half22float2(*(const __half2*)&tr.x);
                float2 tb = __half22float2(*(const __half2*)&tr.y);
                float s = (Qv.x + t0.x) * (kv.x + t1.x) + (Qv.y + t0.y) * (kv.y + t1.y)
                        + (Qv.z + t0.z) * (kv.z + t1.z) + (Qv.w + t0.w) * (kv.w + t1.w);
#pragma unroll
                for (int m = 8; m; m >>= 1) s += __shfl_xor_sync(0xffffffffu, s, m);
                float att = __expf(fmaf(s, sA, bc));
                acc.x = fmaf(gelu_t(vlo.x + ta.x), att, acc.x);
                acc.y = fmaf(gelu_t(vlo.y + ta.y), att, acc.y);
                acc.z = fmaf(gelu_t(vhi.x + tb.x), att, acc.z);
                acc.w = fmaf(gelu_t(vhi.y + tb.y), att, acc.w);
            }
        }
    }
    *(float4*)&g_Agg[v * WIDTH + c4] = acc;
}

extern "C" void kernel_launch(void* const* d_in, const int* in_sizes, int n_in,
                              void* d_out, int out_size)
{
    const float* x        = (const float*)d_in[0];
    const int*   ei       = (const int*)  d_in[1];
    const int*   ea       = (const int*)  d_in[2];
    const float* pre_w    = (const float*)d_in[3];
    const float* pre_b    = (const float*)d_in[4];
    const float* msg0_w   = (const float*)d_in[5];
    const float* msg0_b   = (const float*)d_in[6];
    const float* msg1_w   = (const float*)d_in[7];
    const float* msg1_b   = (const float*)d_in[8];
    const float* msg2_w   = (const float*)d_in[9];
    const float* msg2_b   = (const float*)d_in[10];
    const float* msg3_w   = (const float*)d_in[11];
    const float* msg3_b   = (const float*)d_in[12];
    const float* remix0_w = (const float*)d_in[13];
    const float* remix0_b = (const float*)d_in[14];
    const float* remix1_w = (const float*)d_in[15];
    const float* remix1_b = (const float*)d_in[16];
    const float* remix2_w = (const float*)d_in[17];
    const float* remix2_b = (const float*)d_in[18];
    const float* post_w   = (const float*)d_in[19];
    const float* post_b   = (const float*)d_in[20];
    const float* emb0     = (const float*)d_in[21];
    const float* emb1     = (const float*)d_in[22];
    const float* emb2     = (const float*)d_in[23];
    const float* emb3     = (const float*)d_in[24];
    const float* einit    = (const float*)d_in[25];
    const float* init0    = (const float*)d_in[26];

    int n = in_sizes[0] / WIDTH;
    int e = in_sizes[1] / 2;
    int nt = (n + 63) / 64;

    static cudaStream_t s2 = 0, s3 = 0;
    static cudaEvent_t ev0 = 0, evW = 0, evCSR = 0, evPRE = 0, ev3 = 0;
    if (!s2) {
        cudaFuncSetAttribute(k_mma, cudaFuncAttributeMaxDynamicSharedMemorySize, DSMEM);
        cudaStreamCreateWithFlags(&s2, cudaStreamNonBlocking);
        cudaStreamCreateWithFlags(&s3, cudaStreamNonBlocking);
        cudaEventCreateWithFlags(&ev0, cudaEventDisableTiming);
        cudaEventCreateWithFlags(&evW, cudaEventDisableTiming);
        cudaEventCreateWithFlags(&evCSR, cudaEventDisableTiming);
        cudaEventCreateWithFlags(&evPRE, cudaEventDisableTiming);
        cudaEventCreateWithFlags(&ev3, cudaEventDisableTiming);
    }

    // fork side stream s2: weight images 1..5, tables, CSR build
    cudaEventRecord(ev0, 0);
    cudaStreamWaitEvent(s2, ev0, 0);

    k_prepw<<<40, 256, 0, s2>>>(pre_w, msg1_w, msg2_w, msg3_w, msg0_w, post_w, 1);
    cudaEventRecord(evW, s2);
    dim3 tg(3, 34);
    k_tables<<<tg, 128, 0, s2>>>(remix0_w, remix1_w, remix2_w,
                                 emb0, emb1, emb2, emb3, einit, init0);
    dim3 cg(3, 81);
    k_combine<<<cg, 128, 0, s2>>>();
    k_zero<<<(n + 255) / 256, 256, 0, s2>>>(n);
    k_hist<<<512, 256, 0, s2>>>(ei, e);
    k_scan<<<1, 1024, 0, s2>>>(n, e);
    k_scatter<<<512, 256, 0, s2>>>(ei, ea, e);
    cudaEventRecord(evCSR, s2);

    // main: w0 image, then PRE
    k_prepw<<<8, 256>>>(pre_w, msg1_w, msg2_w, msg3_w, msg0_w, post_w, 0);

    k_mma<<<nt, 512, DSMEM>>>(0, x, pre_b, post_b, msg0_b, msg1_b, msg2_b, msg3_b,
                              remix0_b, remix1_b, remix2_b, init0, (float*)d_out, n);
    cudaEventRecord(evPRE, 0);

    // s3: X2 projection, overlaps QKV + edge
    cudaStreamWaitEvent(s3, evPRE, 0);
    cudaStreamWaitEvent(s3, evW, 0);
    k_mma<<<nt, 512, DSMEM, s3>>>(3, x, pre_b, post_b, msg0_b, msg1_b, msg2_b, msg3_b,
                                  remix0_b, remix1_b, remix2_b, init0, (float*)d_out, n);
    cudaEventRecord(ev3, s3);

    // main: Q,K,V projections
    cudaStreamWaitEvent(0, evW, 0);
    dim3 qg(nt, 3);
    k_mma<<<qg, 512, DSMEM>>>(1, x, pre_b, post_b, msg0_b, msg1_b, msg2_b, msg3_b,
                              remix0_b, remix1_b, remix2_b, init0, (float*)d_out, n);

    // edge phase (needs V + tables + CSR; independent of X2)
    cudaStreamWaitEvent(0, evCSR, 0);
    k_edgec<<<(n + 15) / 16, 512>>>(init0, n);

    // POST: out = x + (X2 + Agg) @ post_w + post_b
    cudaStreamWaitEvent(0, ev3, 0);
    k_mma<<<nt, 512, DSMEM>>>(2, x, pre_b, post_b, msg0_b, msg1_b, msg2_b, msg3_b,
                              remix0_b, remix1_b, remix2_b, init0, (float*)d_out, n);
}

// round 15
// speedup vs baseline: 1.5033x; 1.0516x over previous
#include <cuda_runtime.h>
#include <cuda_bf16.h>
#include <cuda_fp16.h>
#include <math.h>
#include <stdint.h>

#define WIDTH 128
#define NMAX  50176
#define EMAX  512000
#define TILEB 32768                 // full 128x128 bf16 image tile
#define ATILE 16384                 // 64-row half tile
#define DSTRIDE 132
// smem: Bh[32K] Bl[32K] | union( Ah[16K] Al[16K] , Dst[33792] )
#define SOFF_BH 0
#define SOFF_BL 32768
#define SOFF_AH 65536
#define SOFF_AL 81920
#define DSMEM   99328

// ---- scratch (device globals) ----
__device__ float  g_Q [NMAX * WIDTH];
__device__ float  g_K [NMAX * WIDTH];
__device__ __half g_Vh[NMAX * WIDTH];
__device__ float  g_X2 [NMAX * WIDTH];
__device__ float  g_T  [3 * 34 * WIDTH];
__device__ float  g_T81[81 * 3 * WIDTH];
__device__ __half g_T2h[81 * WIDTH];
__device__ unsigned char g_iW[6][2][TILEB];
__device__ unsigned char g_iXh[392 * TILEB];
__device__ unsigned char g_iXl[392 * TILEB];
__device__ int g_cnt [NMAX];
__device__ int g_cur [NMAX];
__device__ int g_base[NMAX + 1];
__device__ int g_esrc[EMAX];
__device__ int g_eidx[EMAX];

__device__ __forceinline__ float gelu1(float x) {
    return 0.5f * x * (1.0f + erff(x * 0.7071067811865475f));
}
__device__ __forceinline__ float gelu_t(float x) {
    float u = 0.7978845608028654f * fmaf(0.044715f * x, x * x, x);
    float t;
    asm("tanh.approx.f32 %0, %1;" : "=f"(t) : "f"(u));
    return 0.5f * x * (1.0f + t);
}
// packed half2 tanh-gelu (edge fast path)
__device__ __forceinline__ __half2 gelu_h2(__half2 x) {
    __half2 x2 = __hmul2(x, x);
    __half2 inner = __hfma2(__hmul2(__float2half2_rn(0.044715f), x2), x, x);
    __half2 u = __hmul2(__float2half2_rn(0.7978845608f), inner);
    uint32_t ur = *(uint32_t*)&u, tr;
    asm("tanh.approx.f16x2 %0, %1;" : "=r"(tr) : "r"(ur));
    __half2 t = *(__half2*)&tr;
    return __hmul2(__hmul2(__float2half2_rn(0.5f), x),
                   __hadd2(t, __float2half2_rn(1.0f)));
}
__device__ __forceinline__ int soff(int row, int kc) {
    return row * 256 + ((kc ^ (row & 7)) << 4);
}
__device__ __forceinline__ uint32_t smem_u32(const void* p) {
    uint32_t a;
    asm("{ .reg .u64 t; cvta.to.shared.u64 t, %1; cvt.u32.u64 %0, t; }" : "=r"(a) : "l"(p));
    return a;
}
__device__ __forceinline__ void cpa16(uint32_t s, const void* g) {
    asm volatile("cp.async.ca.shared.global [%0], [%1], 16;" :: "r"(s), "l"(g));
}
__device__ __forceinline__ void ldm4(uint32_t* r, uint32_t a) {
    asm volatile("ldmatrix.sync.aligned.m8n8.x4.shared.b16 {%0,%1,%2,%3}, [%4];"
                 : "=r"(r[0]), "=r"(r[1]), "=r"(r[2]), "=r"(r[3]) : "r"(a));
}
__device__ __forceinline__ void mma16816(float* c, const uint32_t* a, uint32_t b0, uint32_t b1) {
    asm volatile(
        "mma.sync.aligned.m16n8k16.row.col.f32.bf16.bf16.f32 "
        "{%0,%1,%2,%3}, {%4,%5,%6,%7}, {%8,%9}, {%0,%1,%2,%3};"
        : "+f"(c[0]), "+f"(c[1]), "+f"(c[2]), "+f"(c[3])
        : "r"(a[0]), "r"(a[1]), "r"(a[2]), "r"(a[3]), "r"(b0), "r"(b1));
}

// ============================================================================
// Tables
// ============================================================================
__global__ void k_tables(const float* __restrict__ r0w, const float* __restrict__ r1w,
                         const float* __restrict__ r2w,
                         const float* __restrict__ e0, const float* __restrict__ e1,
                         const float* __restrict__ e2, const float* __restrict__ e3,
                         const float* __restrict__ einit, const float* __restrict__ init0)
{
    int j = blockIdx.x, r = blockIdx.y, o = threadIdx.x;
    int c, lr;
    if (r < 6)       { c = 0; lr = r; }
    else if (r < 13) { c = 1; lr = r - 6; }
    else if (r < 16) { c = 2; lr = r - 13; }
    else             { c = 3; lr = r - 16; }
    const float* emb = (c == 0) ? e0 : (c == 1) ? e1 : (c == 2) ? e2 : e3;
    const float* rw  = (j == 0) ? r0w : (j == 1) ? r1w : r2w;

    __shared__ float er[64];
    if (o < 64) er[o] = emb[lr * 64 + o];
    __syncthreads();

    float s = 0.0f;
#pragma unroll
    for (int m = 0; m < 64; m++) s += er[m] * rw[m * WIDTH + o];

    float es = expf(einit[0]) + expf(einit[1]) + expf(einit[2]) + expf(einit[3]);
    float xw = expf(einit[c]) * rsqrtf(es);
    float sf = expf((j == 2) ? init0[3] : init0[2]);
    g_T[(j * 34 + r) * WIDTH + o] = s * xw * sf;
}

__global__ void k_combine()
{
    int j = blockIdx.x, i = blockIdx.y, o = threadIdx.x;
    int d0 = i % 3, d1 = (i / 3) % 3, d2 = (i / 9) % 3, d3 = i / 27;
    float v = g_T[(j * 34 + d0) * WIDTH + o] + g_T[(j * 34 + 6 + d1) * WIDTH + o]
            + g_T[(j * 34 + 13 + d2) * WIDTH + o] + g_T[(j * 34 + 16 + d3) * WIDTH + o];
    g_T81[(i * 3 + j) * WIDTH + o] = v;
    if (j == 2) g_T2h[i * WIDTH + o] = __float2half(v);
}

// ============================================================================
// CSR build
// ============================================================================
__global__ void k_zero(int n)
{
    int i = blockIdx.x * blockDim.x + threadIdx.x;
    if (i < n) { g_cnt[i] = 0; g_cur[i] = 0; }
}
__global__ void k_hist(const int* __restrict__ ei, int e)
{
    for (int i = blockIdx.x * blockDim.x + threadIdx.x; i < e; i += gridDim.x * blockDim.x)
        atomicAdd(&g_cnt[ei[e + i]], 1);
}
__global__ void __launch_bounds__(1024) k_scan(int n, int e)
{
    __shared__ int sp[1024];
    int t = threadIdx.x;
    int chunk = (n + 1023) >> 10;
    int lo = t * chunk, hi = min(lo + chunk, n);
    int s = 0;
    for (int i = lo; i < hi; i++) s += g_cnt[i];
    sp[t] = s;
    __syncthreads();
    for (int d = 1; d < 1024; d <<= 1) {
        int v = (t >= d) ? sp[t - d] : 0;
        __syncthreads();
        if (t >= d) sp[t] += v;
        __syncthreads();
    }
    int run = (t > 0) ? sp[t - 1] : 0;
    for (int i = lo; i < hi; i++) { int c = g_cnt[i]; g_base[i] = run; run += c; }
    if (t == 0) g_base[n] = e;
}
__global__ void k_scatter(const int* __restrict__ ei, const int* __restrict__ ea, int e)
{
    for (int i = blockIdx.x * blockDim.x + threadIdx.x; i < e; i += gridDim.x * blockDim.x) {
        int dst = ei[e + i];
        int4 a = __ldg((const int4*)ea + i);
        int idx = a.x + 3 * a.y + 9 * a.z + 27 * a.w;
        int pos = g_base[dst] + atomicAdd(&g_cur[dst], 1);
        g_esrc[pos] = ei[i];
        g_eidx[pos] = idx;
    }
}

// ============================================================================
// Weight prep: wi = first + blockIdx.x/8
// ============================================================================
__global__ void __launch_bounds__(256) k_prepw(const float* __restrict__ w0,
    const float* __restrict__ w1, const float* __restrict__ w2,
    const float* __restrict__ w3, const float* __restrict__ w4,
    const float* __restrict__ w5, int first)
{
    int wi = first + (blockIdx.x >> 3), sl = blockIdx.x & 7;
    const float* W = (wi == 0) ? w0 : (wi == 1) ? w1 : (wi == 2) ? w2
                   : (wi == 3) ? w3 : (wi == 4) ? w4 : w5;
    int nrow = sl * 16 + (threadIdx.x >> 4);
    int kc = threadIdx.x & 15;
    __nv_bfloat16 h8[8], l8[8];
#pragma unroll
    for (int j = 0; j < 8; j++) {
        float v = W[(kc * 8 + j) * WIDTH + nrow];
        h8[j] = __float2bfloat16(v);
        l8[j] = __float2bfloat16(v - __bfloat162float(h8[j]));
    }
    int off = soff(nrow, kc);
    *(uint4*)(g_iW[wi][0] + off) = *(uint4*)h8;
    *(uint4*)(g_iW[wi][1] + off) = *(uint4*)l8;
}

// ============================================================================
// mma.sync GEMM: 64x128 tile, 512 thr (warp grid 2x8, 32x16/warp), 2 CTAs/SM.
// bf16 hi/lo 3-pass, pipelined cp.async (group0 = hi, group1 = lo).
// mode 0: PRE -> xx half-images. mode 1: step=blockIdx.y (0=Q,1=K,2=V,3=X2),
//   Q/K self-retire when init0[0]==0. mode 2: POST -> dout.
// ============================================================================
__global__ void __launch_bounds__(512, 2)
k_mma(int mode, const float* __restrict__ x,
      const float* __restrict__ pre_b, const float* __restrict__ post_b,
      const float* __restrict__ m0b, const float* __restrict__ m1b,
      const float* __restrict__ m2b, const float* __restrict__ m3b,
      const float* __restrict__ r0b, const float* __restrict__ r1b,
      const float* __restrict__ r2b,
      const float* __restrict__ init0, float* __restrict__ dout, int n)
{
    extern __shared__ unsigned char sm[];
    const uint32_t sbase = smem_u32(sm);
    const uint32_t sBh = sbase + SOFF_BH, sBl = sbase + SOFF_BL;
    const uint32_t sAh = sbase + SOFF_AH, sAl = sbase + SOFF_AL;
    float* Dst = (float*)(sm + SOFF_AH);    // aliases A (A dead before staging)

    const int tid = threadIdx.x;
    const int wid = tid >> 5, lane = tid & 31;
    const int wr = wid >> 3, wc = wid & 7;      // 2 x 8 warp grid
    const int tile = blockIdx.x, r0 = tile * 64;
    const int step = blockIdx.y;

    if (mode == 1 && step < 2 && __ldg(&init0[0]) == 0.0f) return;

    const int widx = (mode == 0) ? 0 : (mode == 2) ? 5 : (step + 1);

    // group0: B hi (+ A hi for mode 1)
#pragma unroll
    for (int i = 0; i < 4; i++) {
        int idx = tid + i * 512;
        cpa16(sBh + idx * 16, g_iW[widx][0] + idx * 16);
    }
    const unsigned char* aimg = g_iXh + (tile >> 1) * TILEB + (tile & 1) * ATILE;
    const unsigned char* aimgl = g_iXl + (tile >> 1) * TILEB + (tile & 1) * ATILE;
    if (mode == 1) {
#pragma unroll
        for (int i = 0; i < 2; i++) {
            int idx = tid + i * 512;
            cpa16(sAh + idx * 16, aimg + idx * 16);
        }
    }
    asm volatile("cp.async.commit_group;");
    // group1: B lo (+ A lo)
#pragma unroll
    for (int i = 0; i < 4; i++) {
        int idx = tid + i * 512;
        cpa16(sBl + idx * 16, g_iW[widx][1] + idx * 16);
    }
    if (mode == 1) {
#pragma unroll
        for (int i = 0; i < 2; i++) {
            int idx = tid + i * 512;
            cpa16(sAl + idx * 16, aimgl + idx * 16);
        }
    } else {
        // convert A from fp32 source (x or g_X2)
        const float* Asrc = (mode == 0) ? x : g_X2;
#pragma unroll
        for (int it = 0; it < 2; it++) {
            int c = tid + it * 512;
            int row = c >> 4, kc = c & 15;
            int gr = r0 + row;
            float v[8];
            if (gr < n) {
                float4 a = *(const float4*)&Asrc[gr * WIDTH + kc * 8];
                float4 b = *(const float4*)&Asrc[gr * WIDTH + kc * 8 + 4];
                v[0] = a.x; v[1] = a.y; v[2] = a.z; v[3] = a.w;
                v[4] = b.x; v[5] = b.y; v[6] = b.z; v[7] = b.w;
            } else {
#pragma unroll
                for (int j = 0; j < 8; j++) v[j] = 0.0f;
            }
            __nv_bfloat16 h8[8], l8[8];
#pragma unroll
            for (int j = 0; j < 8; j++) {
                h8[j] = __float2bfloat16(v[j]);
                l8[j] = __float2bfloat16(v[j] - __bfloat162float(h8[j]));
            }
            int off = soff(row, kc);
            *(uint4*)(sm + SOFF_AH + off) = *(uint4*)h8;
            *(uint4*)(sm + SOFF_AL + off) = *(uint4*)l8;
        }
    }
    asm volatile("cp.async.commit_group;");
    asm volatile("cp.async.wait_group 1;");     // hi halves ready
    __syncthreads();

    float acc[2][2][4];
#pragma unroll
    for (int i = 0; i < 2; i++)
#pragma unroll
        for (int j = 0; j < 2; j++)
#pragma unroll
            for (int q = 0; q < 4; q++) acc[i][j][q] = 0.0f;

#pragma unroll
    for (int pass = 0; pass < 3; pass++) {
        if (pass == 1) {
            asm volatile("cp.async.wait_group 0;");
            __syncthreads();
        }
        uint32_t Ab = (pass == 2) ? sAl : sAh;
        uint32_t Bb = (pass == 1) ? sBl : sBh;
#pragma unroll
        for (int kk = 0; kk < 8; kk++) {
            uint32_t a[2][4], b[4];
#pragma unroll
            for (int mt = 0; mt < 2; mt++) {
                int row = wr * 32 + mt * 16 + (lane & 15);
                int kc = 2 * kk + (lane >> 4);
                ldm4(a[mt], Ab + soff(row, kc));
            }
            {
                int nn = wc * 16 + (lane & 7) + ((lane >> 4) << 3);
                int kc = 2 * kk + ((lane >> 3) & 1);
                ldm4(b, Bb + soff(nn, kc));
            }
#pragma unroll
            for (int mt = 0; mt < 2; mt++) {
                mma16816(acc[mt][0], a[mt], b[0], b[1]);
                mma16816(acc[mt][1], a[mt], b[2], b[3]);
            }
        }
    }
    __syncthreads();   // A dead -> Dst may overwrite

    // ---- stage fragments ----
#pragma unroll
    for (int mt = 0; mt < 2; mt++)
#pragma unroll
        for (int jn = 0; jn < 2; jn++) {
            int row = wr * 32 + mt * 16 + (lane >> 2);
            int col = wc * 16 + jn * 8 + 2 * (lane & 3);
            Dst[row * DSTRIDE + col]           = acc[mt][jn][0];
            Dst[row * DSTRIDE + col + 1]       = acc[mt][jn][1];
            Dst[(row + 8) * DSTRIDE + col]     = acc[mt][jn][2];
            Dst[(row + 8) * DSTRIDE + col + 1] = acc[mt][jn][3];
        }
    __syncthreads();

    if (mode == 0) {
        float4 bb = __ldg((const float4*)&pre_b[lane * 4]);
#pragma unroll
        for (int r = 0; r < 4; r++) {
            int row = wid * 4 + r;
            float4 v = *(float4*)&Dst[row * DSTRIDE + lane * 4];
            v.x += bb.x; v.y += bb.y; v.z += bb.z; v.w += bb.w;
            float s1 = v.x + v.y + v.z + v.w;
            float s2 = v.x * v.x + v.y * v.y + v.z * v.z + v.w * v.w;
#pragma unroll
            for (int m = 16; m; m >>= 1) {
                s1 += __shfl_xor_sync(0xffffffffu, s1, m);
                s2 += __shfl_xor_sync(0xffffffffu, s2, m);
            }
            float mean = s1 * (1.0f / 128.0f);
            float var  = s2 * (1.0f / 128.0f) - mean * mean;
            float rstd = rsqrtf(var + 1e-5f);
            float4 o = make_float4((v.x - mean) * rstd, (v.y - mean) * rstd,
                                   (v.z - mean) * rstd, (v.w - mean) * rstd);
            *(float4*)&Dst[row * DSTRIDE + lane * 4] = o;
        }
        __syncthreads();
        unsigned char* oh = g_iXh + (tile >> 1) * TILEB + (tile & 1) * ATILE;
        unsigned char* ol = g_iXl + (tile >> 1) * TILEB + (tile & 1) * ATILE;
#pragma unroll
        for (int it = 0; it < 2; it++) {
            int c = tid + it * 512;
            int row = c >> 4, kc = c & 15;
            float4 a = *(float4*)&Dst[row * DSTRIDE + kc * 8];
            float4 b = *(float4*)&Dst[row * DSTRIDE + kc * 8 + 4];
            float v[8] = {a.x, a.y, a.z, a.w, b.x, b.y, b.z, b.w};
            __nv_bfloat16 h8[8], l8[8];
#pragma unroll
            for (int j = 0; j < 8; j++) {
                h8[j] = __float2bfloat16(v[j]);
                l8[j] = __float2bfloat16(v[j] - __bfloat162float(h8[j]));
            }
            int off = soff(row, kc);
            *(uint4*)(oh + off) = *(uint4*)h8;
            *(uint4*)(ol + off) = *(uint4*)l8;
        }
    } else if (mode == 1) {
        const float* b1; const float* b2; float sc;
        float sc_e = expf(__ldg(&init0[2]));
        float sc_v = expf(__ldg(&init0[3]));
        if (step == 0)      { b1 = m1b; b2 = r0b; sc = sc_e; }
        else if (step == 1) { b1 = m2b; b2 = r1b; sc = sc_e; }
        else if (step == 2) { b1 = m3b; b2 = r2b; sc = sc_v; }
        else                { b1 = m0b; b2 = 0;   sc = 0.f; }
        float4 bb = __ldg((const float4*)&b1[lane * 4]);
        if (b2) {
            float4 b2v = __ldg((const float4*)&b2[lane * 4]);
            bb.x += sc * b2v.x; bb.y += sc * b2v.y;
            bb.z += sc * b2v.z; bb.w += sc * b2v.w;
        }
#pragma unroll
        for (int r = 0; r < 4; r++) {
            int row = wid * 4 + r;
            int gr = r0 + row;
            if (gr >= n) continue;
            float4 v = *(float4*)&Dst[row * DSTRIDE + lane * 4];
            v.x += bb.x; v.y += bb.y; v.z += bb.z; v.w += bb.w;
            if (step == 0) {
                *(float4*)&g_Q[gr * WIDTH + lane * 4] = v;
            } else if (step == 1) {
                *(float4*)&g_K[gr * WIDTH + lane * 4] = v;
            } else if (step == 2) {
                __half h4[4] = {__float2half_rn(v.x), __float2half_rn(v.y),
                                __float2half_rn(v.z), __float2half_rn(v.w)};
                *(uint2*)&g_Vh[gr * WIDTH + lane * 4] = *(uint2*)h4;
            } else {
                v.x = gelu1(v.x); v.y = gelu1(v.y);
                v.z = gelu1(v.z); v.w = gelu1(v.w);
                *(float4*)&g_X2[gr * WIDTH + lane * 4] = v;
            }
        }
    } else {
        float4 bb = __ldg((const float4*)&post_b[lane * 4]);
#pragma unroll
        for (int r = 0; r < 4; r++) {
            int row = wid * 4 + r;
            int gr = r0 + row;
            if (gr >= n) continue;
            float4 v = *(float4*)&Dst[row * DSTRIDE + lane * 4];
            float4 xv = __ldg((const float4*)&x[gr * WIDTH + lane * 4]);
            float4 o = make_float4(v.x + bb.x + xv.x, v.y + bb.y + xv.y,
                                   v.z + bb.z + xv.z, v.w + bb.w + xv.w);
            *(float4*)&dout[gr * WIDTH + lane * 4] = o;
        }
    }
}

// ============================================================================
// Edge phase: warp per destination node (CSR), 512 threads (16 nodes/block).
// Fast path: packed f16x2 gelu (tanh.approx.f16x2), fp32 accumulation.
// g_X2[v] += att * sum gelu(V[src]+T2[idx])
// ============================================================================
__global__ void __launch_bounds__(512) k_edgec(const float* __restrict__ init0, int n)
{
    int v = blockIdx.x * 16 + (threadIdx.x >> 5);
    if (v >= n) return;
    int lane = threadIdx.x & 31;
    int b0 = g_base[v], b1 = g_base[v + 1];
    if (b0 == b1) return;
    int c4 = lane << 2;
    float4 acc = make_float4(0.f, 0.f, 0.f, 0.f);

    float a0 = __ldg(&init0[0]);
    float bc = __ldg(&init0[1]);

    if (a0 == 0.0f) {
        int j = b0;
        for (; j + 4 <= b1; j += 4) {
            int s0 = __ldg(&g_esrc[j]),   s1 = __ldg(&g_esrc[j+1]);
            int s2 = __ldg(&g_esrc[j+2]), s3 = __ldg(&g_esrc[j+3]);
            int i0 = __ldg(&g_eidx[j]),   i1 = __ldg(&g_eidx[j+1]);
            int i2 = __ldg(&g_eidx[j+2]), i3 = __ldg(&g_eidx[j+3]);
            uint2 v0 = __ldg((const uint2*)&g_Vh[s0 * WIDTH + c4]);
            uint2 v1 = __ldg((const uint2*)&g_Vh[s1 * WIDTH + c4]);
            uint2 v2 = __ldg((const uint2*)&g_Vh[s2 * WIDTH + c4]);
            uint2 v3 = __ldg((const uint2*)&g_Vh[s3 * WIDTH + c4]);
            uint2 t0 = __ldg((const uint2*)&g_T2h[i0 * WIDTH + c4]);
            uint2 t1 = __ldg((const uint2*)&g_T2h[i1 * WIDTH + c4]);
            uint2 t2 = __ldg((const uint2*)&g_T2h[i2 * WIDTH + c4]);
            uint2 t3 = __ldg((const uint2*)&g_T2h[i3 * WIDTH + c4]);
#pragma unroll
            for (int u = 0; u < 4; u++) {
                uint2 vr = (u == 0) ? v0 : (u == 1) ? v1 : (u == 2) ? v2 : v3;
                uint2 tr = (u == 0) ? t0 : (u == 1) ? t1 : (u == 2) ? t2 : t3;
                __half2 glo = gelu_h2(__hadd2(*(__half2*)&vr.x, *(__half2*)&tr.x));
                __half2 ghi = gelu_h2(__hadd2(*(__half2*)&vr.y, *(__half2*)&tr.y));
                float2 f0 = __half22float2(glo);
                float2 f1 = __half22float2(ghi);
                acc.x += f0.x; acc.y += f0.y; acc.z += f1.x; acc.w += f1.y;
            }
        }
        for (; j < b1; j++) {
            int s0 = __ldg(&g_esrc[j]);
            int i0 = __ldg(&g_eidx[j]);
            uint2 vr = __ldg((const uint2*)&g_Vh[s0 * WIDTH + c4]);
            uint2 tr = __ldg((const uint2*)&g_T2h[i0 * WIDTH + c4]);
            __half2 glo = gelu_h2(__hadd2(*(__half2*)&vr.x, *(__half2*)&tr.x));
            __half2 ghi = gelu_h2(__hadd2(*(__half2*)&vr.y, *(__half2*)&tr.y));
            float2 f0 = __half22float2(glo);
            float2 f1 = __half22float2(ghi);
            acc.x += f0.x; acc.y += f0.y; acc.z += f1.x; acc.w += f1.y;
        }
        float att = __expf(bc);
        acc.x *= att; acc.y *= att; acc.z *= att; acc.w *= att;
    } else {
        const float4* T = (const float4*)g_T81;
        float4 Qv = *(const float4*)&g_Q[v * WIDTH + c4];
        float sA = a0 * 0.125f;
        for (int j = b0; j < b1; j++) {
            int src = __ldg(&g_esrc[j]);
            int idx = __ldg(&g_eidx[j]);
            float4 t0 = __ldg(&T[(idx * 3 + 0) * 32 + lane]);
            float4 t1 = __ldg(&T[(idx * 3 + 1) * 32 + lane]);
            float4 kv = __ldg((const float4*)&g_K[src * WIDTH + c4]);
            uint2 vr = __ldg((const uint2*)&g_Vh[src * WIDTH + c4]);
            uint2 tr = __ldg((const uint2*)&g_T2h[idx * WIDTH + c4]);
            float2 vlo = __half22float2(*(const __half2*)&vr.x);
            float2 vhi = __half22float2(*(const __half2*)&vr.y);
            float2 ta = __half22float2(*(const __half2*)&tr.x);
            float2 tb = __half22float2(*(const __half2*)&tr.y);
            float s = (Qv.x + t0.x) * (kv.x + t1.x) + (Qv.y + t0.y) * (kv.y + t1.y)
                    + (Qv.z + t0.z) * (kv.z + t1.z) + (Qv.w + t0.w) * (kv.w + t1.w);
#pragma unroll
            for (int m = 8; m; m >>= 1) s += __shfl_xor_sync(0xffffffffu, s, m);
            float att = __expf(fmaf(s, sA, bc));
            acc.x = fmaf(gelu_t(vlo.x + ta.x), att, acc.x);
            acc.y = fmaf(gelu_t(vlo.y + ta.y), att, acc.y);
            acc.z = fmaf(gelu_t(vhi.x + tb.x), att, acc.z);
            acc.w = fmaf(gelu_t(vhi.y + tb.y), att, acc.w);
        }
    }

    float* xp = &g_X2[v * WIDTH + c4];
    float4 cur = *(float4*)xp;
    cur.x += acc.x; cur.y += acc.y; cur.z += acc.z; cur.w += acc.w;
    *(float4*)xp = cur;
}

extern "C" void kernel_launch(void* const* d_in, const int* in_sizes, int n_in,
                              void* d_out, int out_size)
{
    const float* x        = (const float*)d_in[0];
    const int*   ei       = (const int*)  d_in[1];
    const int*   ea       = (const int*)  d_in[2];
    const float* pre_w    = (const float*)d_in[3];
    const float* pre_b    = (const float*)d_in[4];
    const float* msg0_w   = (const float*)d_in[5];
    const float* msg0_b   = (const float*)d_in[6];
    const float* msg1_w   = (const float*)d_in[7];
    const float* msg1_b   = (const float*)d_in[8];
    const float* msg2_w   = (const float*)d_in[9];
    const float* msg2_b   = (const float*)d_in[10];
    const float* msg3_w   = (const float*)d_in[11];
    const float* msg3_b   = (const float*)d_in[12];
    const float* remix0_w = (const float*)d_in[13];
    const float* remix0_b = (const float*)d_in[14];
    const float* remix1_w = (const float*)d_in[15];
    const float* remix1_b = (const float*)d_in[16];
    const float* remix2_w = (const float*)d_in[17];
    const float* remix2_b = (const float*)d_in[18];
    const float* post_w   = (const float*)d_in[19];
    const float* post_b   = (const float*)d_in[20];
    const float* emb0     = (const float*)d_in[21];
    const float* emb1     = (const float*)d_in[22];
    const float* emb2     = (const float*)d_in[23];
    const float* emb3     = (const float*)d_in[24];
    const float* einit    = (const float*)d_in[25];
    const float* init0    = (const float*)d_in[26];

    int n = in_sizes[0] / WIDTH;
    int e = in_sizes[1] / 2;
    int nt = (n + 63) / 64;

    static cudaStream_t s2 = 0;
    static cudaEvent_t ev0 = 0, ev1 = 0, ev2 = 0;
    if (!s2) {
        cudaFuncSetAttribute(k_mma, cudaFuncAttributeMaxDynamicSharedMemorySize, DSMEM);
        cudaStreamCreateWithFlags(&s2, cudaStreamNonBlocking);
        cudaEventCreateWithFlags(&ev0, cudaEventDisableTiming);
        cudaEventCreateWithFlags(&ev1, cudaEventDisableTiming);
        cudaEventCreateWithFlags(&ev2, cudaEventDisableTiming);
    }

    // fork side stream: weight images 1..5, tables, CSR build
    cudaEventRecord(ev0, 0);
    cudaStreamWaitEvent(s2, ev0, 0);

    k_prepw<<<40, 256, 0, s2>>>(pre_w, msg1_w, msg2_w, msg3_w, msg0_w, post_w, 1);
    cudaEventRecord(ev2, s2);
    dim3 tg(3, 34);
    k_tables<<<tg, 128, 0, s2>>>(remix0_w, remix1_w, remix2_w,
                                 emb0, emb1, emb2, emb3, einit, init0);
    dim3 cg(3, 81);
    k_combine<<<cg, 128, 0, s2>>>();
    k_zero<<<(n + 255) / 256, 256, 0, s2>>>(n);
    k_hist<<<512, 256, 0, s2>>>(ei, e);
    k_scan<<<1, 1024, 0, s2>>>(n, e);
    k_scatter<<<512, 256, 0, s2>>>(ei, ea, e);
    cudaEventRecord(ev1, s2);

    // main: w0 image only, then PRE
    k_prepw<<<8, 256>>>(pre_w, msg1_w, msg2_w, msg3_w, msg0_w, post_w, 0);

    k_mma<<<nt, 512, DSMEM>>>(0, x, pre_b, post_b, msg0_b, msg1_b, msg2_b, msg3_b,
                              remix0_b, remix1_b, remix2_b, init0, (float*)d_out, n);

    // QKVM needs weight images 1..4 from side stream
    cudaStreamWaitEvent(0, ev2, 0);
    dim3 qg(nt, 4);
    k_mma<<<qg, 512, DSMEM>>>(1, x, pre_b, post_b, msg0_b, msg1_b, msg2_b, msg3_b,
                              remix0_b, remix1_b, remix2_b, init0, (float*)d_out, n);

    // edge phase (needs V + tables + CSR)
    cudaStreamWaitEvent(0, ev1, 0);
    k_edgec<<<(n + 15) / 16, 512>>>(init0, n);

    // POST: out = x + (X2 + agg) @ post_w + post_b
    k_mma<<<nt, 512, DSMEM>>>(2, x, pre_b, post_b, msg0_b, msg1_b, msg2_b, msg3_b,
                              remix0_b, remix1_b, remix2_b, init0, (float*)d_out, n);
}